// round 6
// baseline (speedup 1.0000x reference)
#include <cuda_runtime.h>
#include <cuda_bf16.h>
#include <math_constants.h>
#include <cstdint>

// Problem constants
#define T_SEQ 4096
#define C_EMB 2048
#define HQ 16
#define HKV 4
#define HD 128
#define HD2 64
#define KVD 512   // HKV*HD

// Scratch (device globals; allocation in kernel_launch is forbidden)
__device__ float g_q[T_SEQ * HQ * HD];
__device__ float g_k[T_SEQ * KVD];
__device__ float g_v[T_SEQ * KVD];
__device__ float g_att[T_SEQ * C_EMB];
__device__ float g_xr[T_SEQ * C_EMB];      // tf32-rounded copies
__device__ float g_wqr[C_EMB * C_EMB];
__device__ float g_wkr[C_EMB * KVD];
__device__ float g_wvr[C_EMB * KVD];
__device__ float g_wor[C_EMB * C_EMB];

__device__ __forceinline__ uint32_t f2tf32(float f) {
    uint32_t r;
    asm("cvt.rna.tf32.f32 %0, %1;" : "=r"(r) : "f"(f));
    return r;
}
__device__ __forceinline__ float roundtf(float f) {
    return __uint_as_float(f2tf32(f));
}

__device__ __forceinline__ void mma_tf32(float c[4], const uint32_t a[4],
                                         uint32_t b0, uint32_t b1) {
    asm("mma.sync.aligned.m16n8k8.row.col.f32.tf32.tf32.f32 "
        "{%0,%1,%2,%3}, {%4,%5,%6,%7}, {%8,%9}, {%0,%1,%2,%3};"
        : "+f"(c[0]), "+f"(c[1]), "+f"(c[2]), "+f"(c[3])
        : "r"(a[0]), "r"(a[1]), "r"(a[2]), "r"(a[3]), "r"(b0), "r"(b1));
}

__device__ __forceinline__ void cp_async16(float* smem_dst, const float* gsrc) {
    uint32_t s = (uint32_t)__cvta_generic_to_shared(smem_dst);
    asm volatile("cp.async.cg.shared.global [%0], [%1], 16;\n" :: "r"(s), "l"(gsrc));
}
__device__ __forceinline__ void cp_commit() {
    asm volatile("cp.async.commit_group;\n");
}
__device__ __forceinline__ void cp_wait0() {
    asm volatile("cp.async.wait_group 0;\n");
}
__device__ __forceinline__ void cp_wait1() {
    asm volatile("cp.async.wait_group 1;\n");
}

// ---------------------------------------------------------------------------
// Fused tf32 rounding for all 5 inputs in ONE launch (grid-stride).
// Sizes in float4 units (compile-time).
// ---------------------------------------------------------------------------
#define X4  (T_SEQ * C_EMB / 4)            // 2097152
#define WQ4 (C_EMB * C_EMB / 4)            // 1048576
#define WK4 (C_EMB * KVD / 4)              // 262144
#define WV4 (C_EMB * KVD / 4)
#define WO4 (C_EMB * C_EMB / 4)
#define RTOT (X4 + WQ4 + WK4 + WV4 + WO4)  // 4718080

__global__ __launch_bounds__(256) void round_all_kernel(
    const float4* __restrict__ x,  float4* __restrict__ xo,
    const float4* __restrict__ wq, float4* __restrict__ wqo,
    const float4* __restrict__ wk, float4* __restrict__ wko,
    const float4* __restrict__ wv, float4* __restrict__ wvo,
    const float4* __restrict__ wo, float4* __restrict__ woo)
{
    int stride = gridDim.x * blockDim.x;
    for (int i = blockIdx.x * blockDim.x + threadIdx.x; i < RTOT; i += stride) {
        const float4* src; float4* dst; int j = i;
        if (j < X4)                     { src = x;  dst = xo; }
        else if ((j -= X4) < WQ4)       { src = wq; dst = wqo; }
        else if ((j -= WQ4) < WK4)      { src = wk; dst = wko; }
        else if ((j -= WK4) < WV4)      { src = wv; dst = wvo; }
        else { j -= WV4;                  src = wo; dst = woo; }
        float4 v = src[j];
        v.x = roundtf(v.x); v.y = roundtf(v.y);
        v.z = roundtf(v.z); v.w = roundtf(v.w);
        dst[j] = v;
    }
}

// ---------------------------------------------------------------------------
// TF32 GEMM, cp.async 3-stage pipeline, single __syncthreads per k-iter.
// C[M,N] = A[M,K] @ B[K,N]. Block 128x128x32, 256 thr, warp tile 32x64.
// round_out: tf32-round C on store (for V).
// ---------------------------------------------------------------------------
#define BM 128
#define BN 128
#define BK 32
#define AST 36
#define BST 136
#define AWORDS (BM * AST)                  // 4608
#define GSTGW (AWORDS + BK * BST)          // 8960 words
#define GEMM_SMEM (GSTGW * 3 * 4)          // 107520 bytes

__global__ __launch_bounds__(256) void gemm_async(
    const float* __restrict__ A, const float* __restrict__ B0,
    const float* __restrict__ B1, float* __restrict__ C0,
    float* __restrict__ C1, int M, int N, int K, int round_z1)
{
    extern __shared__ __align__(16) float sm[];

    const float* B = (blockIdx.z == 0) ? B0 : B1;
    float* C       = (blockIdx.z == 0) ? C0 : C1;
    int round_out  = (blockIdx.z == 0) ? 0 : round_z1;

    int tid = threadIdx.x;
    int bx = blockIdx.x, by = blockIdx.y;
    int lane = tid & 31, warp = tid >> 5;
    int wm = (warp >> 1) * 32, wn = (warp & 1) * 64;
    int gr = lane >> 2, tg = lane & 3;

    const float* Ab = A + (size_t)by * BM * K;
    const float* Bb = B + (size_t)bx * BN;

    auto issue = [&](int kt, int s) {
        float* As = sm + s * GSTGW;
        float* Bs = As + AWORDS;
        int k0 = kt * BK;
#pragma unroll
        for (int i = 0; i < 4; i++) {
            int c = tid + i * 256;
            int r = c >> 3, cc = c & 7;
            cp_async16(As + r * AST + cc * 4, Ab + (size_t)r * K + k0 + cc * 4);
        }
#pragma unroll
        for (int i = 0; i < 4; i++) {
            int c = tid + i * 256;
            int r = c >> 5, cc = c & 31;
            cp_async16(Bs + r * BST + cc * 4, Bb + (size_t)(k0 + r) * N + cc * 4);
        }
        cp_commit();
    };

    float acc[2][8][4];
#pragma unroll
    for (int i = 0; i < 2; i++)
#pragma unroll
        for (int j = 0; j < 8; j++)
#pragma unroll
            for (int q = 0; q < 4; q++) acc[i][j][q] = 0.f;

    int nk = K / BK;
    issue(0, 0);
    issue(1, 1);

    for (int kt = 0; kt < nk; kt++) {
        // Ensure stage kt%3 has landed. On the last iter its group is the
        // newest -> full drain required.
        if (kt == nk - 1) cp_wait0(); else cp_wait1();
        __syncthreads();   // all warps done with stage (kt-1)%3 == (kt+2)%3
        if (kt + 2 < nk) issue(kt + 2, (kt + 2) % 3);

        const float* As = sm + (kt % 3) * GSTGW;
        const float* Bs = As + AWORDS;

#pragma unroll
        for (int kk = 0; kk < 4; kk++) {
            int k0 = kk * 8;
            uint32_t a[2][4];
#pragma unroll
            for (int i = 0; i < 2; i++) {
                int m0 = wm + i * 16 + gr;
                a[i][0] = __float_as_uint(As[m0 * AST + k0 + tg]);
                a[i][1] = __float_as_uint(As[(m0 + 8) * AST + k0 + tg]);
                a[i][2] = __float_as_uint(As[m0 * AST + k0 + tg + 4]);
                a[i][3] = __float_as_uint(As[(m0 + 8) * AST + k0 + tg + 4]);
            }
#pragma unroll
            for (int j = 0; j < 8; j++) {
                uint32_t b0 = __float_as_uint(Bs[(k0 + tg) * BST + wn + j * 8 + gr]);
                uint32_t b1 = __float_as_uint(Bs[(k0 + tg + 4) * BST + wn + j * 8 + gr]);
                mma_tf32(acc[0][j], a[0], b0, b1);
                mma_tf32(acc[1][j], a[1], b0, b1);
            }
        }
    }

#pragma unroll
    for (int i = 0; i < 2; i++) {
#pragma unroll
        for (int j = 0; j < 8; j++) {
            int r0 = by * BM + wm + i * 16 + gr;
            int cc = bx * BN + wn + j * 8 + 2 * tg;
            float2 v0 = { acc[i][j][0], acc[i][j][1] };
            float2 v1 = { acc[i][j][2], acc[i][j][3] };
            if (round_out) {
                v0.x = roundtf(v0.x); v0.y = roundtf(v0.y);
                v1.x = roundtf(v1.x); v1.y = roundtf(v1.y);
            }
            *(float2*)(C + (size_t)r0 * N + cc) = v0;
            *(float2*)(C + (size_t)(r0 + 8) * N + cc) = v1;
        }
    }
}

// ---------------------------------------------------------------------------
// Fused RoPE + RMSNorm for Q and K in one launch.
// Block = 256 threads = 4 groups of 64; grid (T, 5): head slot = y*4+g;
// slots 0..15 -> Q head, 16..19 -> K head (K output tf32-rounded).
// ---------------------------------------------------------------------------
__global__ __launch_bounds__(256) void rope_rms_fused(
    float* __restrict__ XQ, float* __restrict__ XK,
    const float* __restrict__ cosp, const float* __restrict__ sinp)
{
    int t = blockIdx.x;
    int g = threadIdx.x >> 6;       // group 0..3
    int i = threadIdx.x & 63;       // 0..63
    int slot = blockIdx.y * 4 + g;  // 0..19

    float* xp;
    int do_round;
    if (slot < HQ) { xp = XQ + ((size_t)t * HQ + slot) * HD;        do_round = 0; }
    else           { xp = XK + ((size_t)t * HKV + (slot - HQ)) * HD; do_round = 1; }

    float x1 = xp[i], x2 = xp[i + HD2];
    float c = cosp[t * HD2 + i];
    float s = sinp[t * HD2 + i];
    float y1 = x1 * c + x2 * s;
    float y2 = x2 * c - x1 * s;

    float ss = y1 * y1 + y2 * y2;
#pragma unroll
    for (int off = 16; off; off >>= 1)
        ss += __shfl_xor_sync(0xffffffffu, ss, off);

    __shared__ float s2[8];          // 2 warps per group
    int warp_in_grp = (i >> 5);      // 0 or 1
    if ((i & 31) == 0) s2[g * 2 + warp_in_grp] = ss;
    __syncthreads();
    float tot = s2[g * 2] + s2[g * 2 + 1];
    float r = rsqrtf(tot * (1.0f / HD) + 1e-6f);

    float o1 = y1 * r, o2 = y2 * r;
    if (do_round) { o1 = roundtf(o1); o2 = roundtf(o2); }
    xp[i]       = o1;
    xp[i + HD2] = o2;
}

// ---------------------------------------------------------------------------
// TF32 flash attention, cp.async 3-stage K/V pipeline, one sync per tile.
// Block = (64 q-rows, 1 head), 4 warps. Blocks scheduled longest-first.
// Output stored tf32-rounded (feeds the O projection directly).
// ---------------------------------------------------------------------------
#define FBQ 64
#define FBK 32
#define KSTW 132
#define VSTW 136
#define FSTGW (FBK * KSTW + FBK * VSTW)       // 8576 words / stage
#define PSOFF (3 * FSTGW)                     // 25728
#define PST 36
#define FLASH_SMEM ((PSOFF + FBQ * PST) * 4)  // 112128 bytes

__global__ __launch_bounds__(128) void flash_async(
    const float* __restrict__ Q, const float* __restrict__ K,
    const float* __restrict__ V, float* __restrict__ O)
{
    extern __shared__ __align__(16) float sm[];

    int h  = blockIdx.y;
    int hk = h >> 2;
    int qb = (gridDim.x - 1 - blockIdx.x) * FBQ;   // longest-work blocks first
    int tid = threadIdx.x;
    int lane = tid & 31, warp = tid >> 5;
    int wm = warp * 16;
    int gr = lane >> 2, tg = lane & 3;

    auto issue = [&](int it, int s) {
        float* Ks = sm + s * FSTGW;
        float* Vs = Ks + FBK * KSTW;
        int kb = it * FBK;
#pragma unroll
        for (int i = 0; i < 8; i++) {
            int c = tid + i * 128;
            int r = c >> 5, cc = c & 31;
            const float* kg = K + ((size_t)(kb + r) * HKV + hk) * HD + cc * 4;
            const float* vg = V + ((size_t)(kb + r) * HKV + hk) * HD + cc * 4;
            cp_async16(Ks + r * KSTW + cc * 4, kg);
            cp_async16(Vs + r * VSTW + cc * 4, vg);
        }
        cp_commit();
    };

    const float scale = 0.08838834764831845f;   // 1/sqrt(128)

    uint32_t qf[16][4];
    int t0 = qb + wm + gr;
    int t1 = t0 + 8;
    const float* q0 = Q + ((size_t)t0 * HQ + h) * HD;
    const float* q1 = Q + ((size_t)t1 * HQ + h) * HD;
#pragma unroll
    for (int ks = 0; ks < 16; ks++) {
        int c = ks * 8 + tg;
        qf[ks][0] = f2tf32(q0[c] * scale);
        qf[ks][1] = f2tf32(q1[c] * scale);
        qf[ks][2] = f2tf32(q0[c + 4] * scale);
        qf[ks][3] = f2tf32(q1[c + 4] * scale);
    }

    float oacc[16][4];
#pragma unroll
    for (int f = 0; f < 16; f++)
#pragma unroll
        for (int q = 0; q < 4; q++) oacc[f][q] = 0.f;
    float m0 = -CUDART_INF_F, m1 = -CUDART_INF_F;
    float l0 = 0.f, l1 = 0.f;

    int nt = (qb + FBQ) / FBK;   // tiles 0..nt-1 (>= 2)
    issue(0, 0);
    issue(1, 1);

    for (int it = 0; it < nt; it++) {
        if (it == nt - 1) cp_wait0(); else cp_wait1();
        __syncthreads();
        if (it + 2 < nt) issue(it + 2, (it + 2) % 3);

        const float* Ks = sm + (it % 3) * FSTGW;
        const float* Vs = Ks + FBK * KSTW;
        float* Ps = sm + PSOFF;
        int kb = it * FBK;

        // S = (Q*scale) @ K^T
        float sacc[4][4];
#pragma unroll
        for (int j = 0; j < 4; j++)
#pragma unroll
            for (int q = 0; q < 4; q++) sacc[j][q] = 0.f;

#pragma unroll
        for (int ks = 0; ks < 16; ks++) {
            int k0 = ks * 8;
#pragma unroll
            for (int j = 0; j < 4; j++) {
                uint32_t b0 = __float_as_uint(Ks[(j * 8 + gr) * KSTW + k0 + tg]);
                uint32_t b1 = __float_as_uint(Ks[(j * 8 + gr) * KSTW + k0 + 4 + tg]);
                mma_tf32(sacc[j], qf[ks], b0, b1);
            }
        }

        // causal mask + row max
        float tm0 = -CUDART_INF_F, tm1 = -CUDART_INF_F;
#pragma unroll
        for (int j = 0; j < 4; j++) {
            int kcol = kb + j * 8 + 2 * tg;
            if (kcol     > t0) sacc[j][0] = -CUDART_INF_F;
            if (kcol + 1 > t0) sacc[j][1] = -CUDART_INF_F;
            if (kcol     > t1) sacc[j][2] = -CUDART_INF_F;
            if (kcol + 1 > t1) sacc[j][3] = -CUDART_INF_F;
            tm0 = fmaxf(tm0, fmaxf(sacc[j][0], sacc[j][1]));
            tm1 = fmaxf(tm1, fmaxf(sacc[j][2], sacc[j][3]));
        }
        tm0 = fmaxf(tm0, __shfl_xor_sync(0xffffffffu, tm0, 1));
        tm0 = fmaxf(tm0, __shfl_xor_sync(0xffffffffu, tm0, 2));
        tm1 = fmaxf(tm1, __shfl_xor_sync(0xffffffffu, tm1, 1));
        tm1 = fmaxf(tm1, __shfl_xor_sync(0xffffffffu, tm1, 2));

        float mn0 = fmaxf(m0, tm0);
        float mn1 = fmaxf(m1, tm1);
        float c0 = __expf(m0 - mn0);
        float c1 = __expf(m1 - mn1);

        float ps0 = 0.f, ps1 = 0.f;
#pragma unroll
        for (int j = 0; j < 4; j++) {
            uint32_t p0 = f2tf32(__expf(sacc[j][0] - mn0));
            uint32_t p1 = f2tf32(__expf(sacc[j][1] - mn0));
            uint32_t p2 = f2tf32(__expf(sacc[j][2] - mn1));
            uint32_t p3 = f2tf32(__expf(sacc[j][3] - mn1));
            ps0 += __uint_as_float(p0) + __uint_as_float(p1);
            ps1 += __uint_as_float(p2) + __uint_as_float(p3);
            uint2 w0 = { p0, p1 };
            uint2 w1 = { p2, p3 };
            *(uint2*)(Ps + (wm + gr) * PST + j * 8 + 2 * tg)     = w0;
            *(uint2*)(Ps + (wm + 8 + gr) * PST + j * 8 + 2 * tg) = w1;
        }
        ps0 += __shfl_xor_sync(0xffffffffu, ps0, 1);
        ps0 += __shfl_xor_sync(0xffffffffu, ps0, 2);
        ps1 += __shfl_xor_sync(0xffffffffu, ps1, 1);
        ps1 += __shfl_xor_sync(0xffffffffu, ps1, 2);

        l0 = l0 * c0 + ps0;
        l1 = l1 * c1 + ps1;
        m0 = mn0; m1 = mn1;

#pragma unroll
        for (int f = 0; f < 16; f++) {
            oacc[f][0] *= c0; oacc[f][1] *= c0;
            oacc[f][2] *= c1; oacc[f][3] *= c1;
        }
        __syncwarp();   // P writes visible within warp

        // O += P @ V
#pragma unroll
        for (int ks2 = 0; ks2 < 4; ks2++) {
            int k0 = ks2 * 8;
            uint32_t a[4];
            a[0] = __float_as_uint(Ps[(wm + gr) * PST + k0 + tg]);
            a[1] = __float_as_uint(Ps[(wm + 8 + gr) * PST + k0 + tg]);
            a[2] = __float_as_uint(Ps[(wm + gr) * PST + k0 + 4 + tg]);
            a[3] = __float_as_uint(Ps[(wm + 8 + gr) * PST + k0 + 4 + tg]);
#pragma unroll
            for (int f = 0; f < 16; f++) {
                uint32_t b0 = __float_as_uint(Vs[(k0 + tg) * VSTW + f * 8 + gr]);
                uint32_t b1 = __float_as_uint(Vs[(k0 + 4 + tg) * VSTW + f * 8 + gr]);
                mma_tf32(oacc[f], a, b0, b1);
            }
        }
    }

    // epilogue: tf32-rounded store (feeds O projection's cp.async path)
    float inv0 = 1.0f / l0;
    float inv1 = 1.0f / l1;
    float* o0 = O + ((size_t)t0 * HQ + h) * HD;
    float* o1 = O + ((size_t)t1 * HQ + h) * HD;
#pragma unroll
    for (int f = 0; f < 16; f++) {
        int cc = f * 8 + 2 * tg;
        float2 v0 = { roundtf(oacc[f][0] * inv0), roundtf(oacc[f][1] * inv0) };
        float2 v1 = { roundtf(oacc[f][2] * inv1), roundtf(oacc[f][3] * inv1) };
        *(float2*)(o0 + cc) = v0;
        *(float2*)(o1 + cc) = v1;
    }
}

// ---------------------------------------------------------------------------
// Launch
// ---------------------------------------------------------------------------
extern "C" void kernel_launch(void* const* d_in, const int* in_sizes, int n_in,
                              void* d_out, int out_size)
{
    const float* x   = (const float*)d_in[0];
    const float* cs  = (const float*)d_in[1];
    const float* sn  = (const float*)d_in[2];
    const float* wq  = (const float*)d_in[3];
    const float* wk  = (const float*)d_in[4];
    const float* wv  = (const float*)d_in[5];
    const float* wo  = (const float*)d_in[6];
    float* out = (float*)d_out;

    float *pq, *pk, *pv, *patt, *pxr, *pwqr, *pwkr, *pwvr, *pwor;
    cudaGetSymbolAddress((void**)&pq,   g_q);
    cudaGetSymbolAddress((void**)&pk,   g_k);
    cudaGetSymbolAddress((void**)&pv,   g_v);
    cudaGetSymbolAddress((void**)&patt, g_att);
    cudaGetSymbolAddress((void**)&pxr,  g_xr);
    cudaGetSymbolAddress((void**)&pwqr, g_wqr);
    cudaGetSymbolAddress((void**)&pwkr, g_wkr);
    cudaGetSymbolAddress((void**)&pwvr, g_wvr);
    cudaGetSymbolAddress((void**)&pwor, g_wor);

    cudaFuncSetAttribute(gemm_async, cudaFuncAttributeMaxDynamicSharedMemorySize,
                         GEMM_SMEM);
    cudaFuncSetAttribute(flash_async, cudaFuncAttributeMaxDynamicSharedMemorySize,
                         FLASH_SMEM);

    // All tf32 pre-rounding in one launch
    round_all_kernel<<<2048, 256>>>(
        (const float4*)x,  (float4*)pxr,
        (const float4*)wq, (float4*)pwqr,
        (const float4*)wk, (float4*)pwkr,
        (const float4*)wv, (float4*)pwvr,
        (const float4*)wo, (float4*)pwor);

    // Q projection
    gemm_async<<<dim3(C_EMB / BN, T_SEQ / BM, 1), 256, GEMM_SMEM>>>(
        pxr, pwqr, pwqr, pq, pq, T_SEQ, C_EMB, C_EMB, 0);
    // K + V projections combined (z picks weight/output; V output rounded)
    gemm_async<<<dim3(KVD / BN, T_SEQ / BM, 2), 256, GEMM_SMEM>>>(
        pxr, pwkr, pwvr, pk, pv, T_SEQ, KVD, C_EMB, 1);

    // RoPE + RMSNorm on Q and K fused (K output tf32-rounded)
    rope_rms_fused<<<dim3(T_SEQ, (HQ + HKV) / 4), 256>>>(pq, pk, cs, sn);

    // Flash attention (output tf32-rounded)
    flash_async<<<dim3(T_SEQ / FBQ, HQ), 128, FLASH_SMEM>>>(pq, pk, pv, patt);

    // Output projection -> d_out
    gemm_async<<<dim3(C_EMB / BN, T_SEQ / BM, 1), 256, GEMM_SMEM>>>(
        patt, pwor, pwor, out, out, T_SEQ, C_EMB, C_EMB, 0);
}

// round 7
// speedup vs baseline: 1.1907x; 1.1907x over previous
#include <cuda_runtime.h>
#include <cuda_bf16.h>
#include <math_constants.h>
#include <cstdint>

// Problem constants
#define T_SEQ 4096
#define C_EMB 2048
#define HQ 16
#define HKV 4
#define HD 128
#define HD2 64
#define KVD 512   // HKV*HD

// Scratch (device globals; allocation in kernel_launch is forbidden)
__device__ float g_q[T_SEQ * HQ * HD];
__device__ float g_k[T_SEQ * KVD];
__device__ float g_v[T_SEQ * KVD];
__device__ float g_att[T_SEQ * C_EMB];
__device__ float g_xr[T_SEQ * C_EMB];      // tf32-rounded copies
__device__ float g_wqr[C_EMB * C_EMB];
__device__ float g_wkr[C_EMB * KVD];
__device__ float g_wvr[C_EMB * KVD];
__device__ float g_wor[C_EMB * C_EMB];

__device__ __forceinline__ uint32_t f2tf32(float f) {
    uint32_t r;
    asm("cvt.rna.tf32.f32 %0, %1;" : "=r"(r) : "f"(f));
    return r;
}
__device__ __forceinline__ float roundtf(float f) {
    return __uint_as_float(f2tf32(f));
}

__device__ __forceinline__ void mma_tf32(float c[4], const uint32_t a[4],
                                         uint32_t b0, uint32_t b1) {
    asm("mma.sync.aligned.m16n8k8.row.col.f32.tf32.tf32.f32 "
        "{%0,%1,%2,%3}, {%4,%5,%6,%7}, {%8,%9}, {%0,%1,%2,%3};"
        : "+f"(c[0]), "+f"(c[1]), "+f"(c[2]), "+f"(c[3])
        : "r"(a[0]), "r"(a[1]), "r"(a[2]), "r"(a[3]), "r"(b0), "r"(b1));
}

__device__ __forceinline__ void cp_async16(float* smem_dst, const float* gsrc) {
    uint32_t s = (uint32_t)__cvta_generic_to_shared(smem_dst);
    asm volatile("cp.async.cg.shared.global [%0], [%1], 16;\n" :: "r"(s), "l"(gsrc));
}
__device__ __forceinline__ void cp_commit() {
    asm volatile("cp.async.commit_group;\n");
}
__device__ __forceinline__ void cp_wait1() {
    asm volatile("cp.async.wait_group 1;\n");
}
__device__ __forceinline__ void cp_wait2() {
    asm volatile("cp.async.wait_group 2;\n");
}

// ---------------------------------------------------------------------------
// Fused tf32 rounding for all 5 inputs in ONE launch (grid-stride).
// ---------------------------------------------------------------------------
#define X4  (T_SEQ * C_EMB / 4)
#define WQ4 (C_EMB * C_EMB / 4)
#define WK4 (C_EMB * KVD / 4)
#define WV4 (C_EMB * KVD / 4)
#define RTOT (X4 + WQ4 + WK4 + WV4 + WQ4)

__global__ __launch_bounds__(256) void round_all_kernel(
    const float4* __restrict__ x,  float4* __restrict__ xo,
    const float4* __restrict__ wq, float4* __restrict__ wqo,
    const float4* __restrict__ wk, float4* __restrict__ wko,
    const float4* __restrict__ wv, float4* __restrict__ wvo,
    const float4* __restrict__ wo, float4* __restrict__ woo)
{
    int stride = gridDim.x * blockDim.x;
    for (int i = blockIdx.x * blockDim.x + threadIdx.x; i < RTOT; i += stride) {
        const float4* src; float4* dst; int j = i;
        if (j < X4)                { src = x;  dst = xo; }
        else if ((j -= X4) < WQ4)  { src = wq; dst = wqo; }
        else if ((j -= WQ4) < WK4) { src = wk; dst = wko; }
        else if ((j -= WK4) < WV4) { src = wv; dst = wvo; }
        else { j -= WV4;             src = wo; dst = woo; }
        float4 v = src[j];
        v.x = roundtf(v.x); v.y = roundtf(v.y);
        v.z = roundtf(v.z); v.w = roundtf(v.w);
        dst[j] = v;
    }
}

// ---------------------------------------------------------------------------
// TF32 GEMM with cp.async 3-stage pipeline — EXACT round-5 pipeline structure
// (wait_group 2, two syncs per iter). grid.z selects (B,C) pair; round flag
// applies tf32 rounding on store for z==1 (V output).
// ---------------------------------------------------------------------------
#define BM 128
#define BN 128
#define BK 32
#define AST 36
#define BST 136
#define AWORDS (BM * AST)
#define GSTGW (AWORDS + BK * BST)          // 8960 words
#define GEMM_SMEM (GSTGW * 3 * 4)          // 107520 bytes

__global__ __launch_bounds__(256) void gemm_async(
    const float* __restrict__ A, const float* __restrict__ B0,
    const float* __restrict__ B1, float* __restrict__ C0,
    float* __restrict__ C1, int M, int N, int K, int round_z1)
{
    extern __shared__ __align__(16) float sm[];

    const float* B = (blockIdx.z == 0) ? B0 : B1;
    float* C       = (blockIdx.z == 0) ? C0 : C1;
    int round_out  = (blockIdx.z == 0) ? 0 : round_z1;

    int tid = threadIdx.x;
    int bx = blockIdx.x, by = blockIdx.y;
    int lane = tid & 31, warp = tid >> 5;
    int wm = (warp >> 1) * 32, wn = (warp & 1) * 64;
    int gr = lane >> 2, tg = lane & 3;

    const float* Ab = A + (size_t)by * BM * K;
    const float* Bb = B + (size_t)bx * BN;

    auto issue = [&](int kt, int s) {
        float* As = sm + s * GSTGW;
        float* Bs = As + AWORDS;
        int k0 = kt * BK;
#pragma unroll
        for (int i = 0; i < 4; i++) {
            int c = tid + i * 256;
            int r = c >> 3, cc = c & 7;
            cp_async16(As + r * AST + cc * 4, Ab + (size_t)r * K + k0 + cc * 4);
        }
#pragma unroll
        for (int i = 0; i < 4; i++) {
            int c = tid + i * 256;
            int r = c >> 5, cc = c & 31;
            cp_async16(Bs + r * BST + cc * 4, Bb + (size_t)(k0 + r) * N + cc * 4);
        }
        cp_commit();
    };

    float acc[2][8][4];
#pragma unroll
    for (int i = 0; i < 2; i++)
#pragma unroll
        for (int j = 0; j < 8; j++)
#pragma unroll
            for (int q = 0; q < 4; q++) acc[i][j][q] = 0.f;

    int nk = K / BK;
    issue(0, 0);
    issue(1, 1);

    for (int kt = 0; kt < nk; kt++) {
        if (kt + 2 < nk) issue(kt + 2, (kt + 2) % 3);
        else cp_commit();          // positional wait: keeps group count uniform
        cp_wait2();
        __syncthreads();

        const float* As = sm + (kt % 3) * GSTGW;
        const float* Bs = As + AWORDS;

#pragma unroll
        for (int kk = 0; kk < 4; kk++) {
            int k0 = kk * 8;
            uint32_t a[2][4];
#pragma unroll
            for (int i = 0; i < 2; i++) {
                int m0 = wm + i * 16 + gr;
                a[i][0] = __float_as_uint(As[m0 * AST + k0 + tg]);
                a[i][1] = __float_as_uint(As[(m0 + 8) * AST + k0 + tg]);
                a[i][2] = __float_as_uint(As[m0 * AST + k0 + tg + 4]);
                a[i][3] = __float_as_uint(As[(m0 + 8) * AST + k0 + tg + 4]);
            }
#pragma unroll
            for (int j = 0; j < 8; j++) {
                uint32_t b0 = __float_as_uint(Bs[(k0 + tg) * BST + wn + j * 8 + gr]);
                uint32_t b1 = __float_as_uint(Bs[(k0 + tg + 4) * BST + wn + j * 8 + gr]);
                mma_tf32(acc[0][j], a[0], b0, b1);
                mma_tf32(acc[1][j], a[1], b0, b1);
            }
        }
        __syncthreads();
    }

#pragma unroll
    for (int i = 0; i < 2; i++) {
#pragma unroll
        for (int j = 0; j < 8; j++) {
            int r0 = by * BM + wm + i * 16 + gr;
            int cc = bx * BN + wn + j * 8 + 2 * tg;
            float2 v0 = { acc[i][j][0], acc[i][j][1] };
            float2 v1 = { acc[i][j][2], acc[i][j][3] };
            if (round_out) {
                v0.x = roundtf(v0.x); v0.y = roundtf(v0.y);
                v1.x = roundtf(v1.x); v1.y = roundtf(v1.y);
            }
            *(float2*)(C + (size_t)r0 * N + cc) = v0;
            *(float2*)(C + (size_t)(r0 + 8) * N + cc) = v1;
        }
    }
}

// ---------------------------------------------------------------------------
// Fused RoPE + RMSNorm for Q and K in one launch.
// Block 256 = 4 groups of 64; grid (T, 5): slot = y*4+g; slots 0..15 Q,
// 16..19 K (K output tf32-rounded).
// ---------------------------------------------------------------------------
__global__ __launch_bounds__(256) void rope_rms_fused(
    float* __restrict__ XQ, float* __restrict__ XK,
    const float* __restrict__ cosp, const float* __restrict__ sinp)
{
    int t = blockIdx.x;
    int g = threadIdx.x >> 6;
    int i = threadIdx.x & 63;
    int slot = blockIdx.y * 4 + g;

    float* xp;
    int do_round;
    if (slot < HQ) { xp = XQ + ((size_t)t * HQ + slot) * HD;         do_round = 0; }
    else           { xp = XK + ((size_t)t * HKV + (slot - HQ)) * HD; do_round = 1; }

    float x1 = xp[i], x2 = xp[i + HD2];
    float c = cosp[t * HD2 + i];
    float s = sinp[t * HD2 + i];
    float y1 = x1 * c + x2 * s;
    float y2 = x2 * c - x1 * s;

    float ss = y1 * y1 + y2 * y2;
#pragma unroll
    for (int off = 16; off; off >>= 1)
        ss += __shfl_xor_sync(0xffffffffu, ss, off);

    __shared__ float s2[8];
    int warp_in_grp = (i >> 5);
    if ((i & 31) == 0) s2[g * 2 + warp_in_grp] = ss;
    __syncthreads();
    float tot = s2[g * 2] + s2[g * 2 + 1];
    float r = rsqrtf(tot * (1.0f / HD) + 1e-6f);

    float o1 = y1 * r, o2 = y2 * r;
    if (do_round) { o1 = roundtf(o1); o2 = roundtf(o2); }
    xp[i]       = o1;
    xp[i + HD2] = o2;
}

// ---------------------------------------------------------------------------
// TF32 flash attention — EXACT round-5 pipeline (2-stage, 77.8 KB smem,
// wait_group 1, two syncs, natural block order). Only change: epilogue
// stores tf32-rounded output.
// ---------------------------------------------------------------------------
#define FBQ 64
#define FBK 32
#define KSTW 132
#define VSTW 136
#define FSTGW (FBK * KSTW + FBK * VSTW)       // 8576 words / stage
#define PSOFF (2 * FSTGW)                     // 17152
#define PST 36
#define FLASH_SMEM ((PSOFF + FBQ * PST) * 4)  // 77824 bytes

__global__ __launch_bounds__(128) void flash_async(
    const float* __restrict__ Q, const float* __restrict__ K,
    const float* __restrict__ V, float* __restrict__ O)
{
    extern __shared__ __align__(16) float sm[];

    int h  = blockIdx.y;
    int hk = h >> 2;
    int qb = blockIdx.x * FBQ;
    int tid = threadIdx.x;
    int lane = tid & 31, warp = tid >> 5;
    int wm = warp * 16;
    int gr = lane >> 2, tg = lane & 3;

    auto issue = [&](int it, int s) {
        float* Ks = sm + s * FSTGW;
        float* Vs = Ks + FBK * KSTW;
        int kb = it * FBK;
#pragma unroll
        for (int i = 0; i < 8; i++) {
            int c = tid + i * 128;
            int r = c >> 5, cc = c & 31;
            const float* kg = K + ((size_t)(kb + r) * HKV + hk) * HD + cc * 4;
            const float* vg = V + ((size_t)(kb + r) * HKV + hk) * HD + cc * 4;
            cp_async16(Ks + r * KSTW + cc * 4, kg);
            cp_async16(Vs + r * VSTW + cc * 4, vg);
        }
        cp_commit();
    };

    const float scale = 0.08838834764831845f;   // 1/sqrt(128)

    uint32_t qf[16][4];
    int t0 = qb + wm + gr;
    int t1 = t0 + 8;
    const float* q0 = Q + ((size_t)t0 * HQ + h) * HD;
    const float* q1 = Q + ((size_t)t1 * HQ + h) * HD;
#pragma unroll
    for (int ks = 0; ks < 16; ks++) {
        int c = ks * 8 + tg;
        qf[ks][0] = f2tf32(q0[c] * scale);
        qf[ks][1] = f2tf32(q1[c] * scale);
        qf[ks][2] = f2tf32(q0[c + 4] * scale);
        qf[ks][3] = f2tf32(q1[c + 4] * scale);
    }

    float oacc[16][4];
#pragma unroll
    for (int f = 0; f < 16; f++)
#pragma unroll
        for (int q = 0; q < 4; q++) oacc[f][q] = 0.f;
    float m0 = -CUDART_INF_F, m1 = -CUDART_INF_F;
    float l0 = 0.f, l1 = 0.f;

    int nt = (qb + FBQ) / FBK;
    issue(0, 0);

    for (int it = 0; it < nt; it++) {
        if (it + 1 < nt) issue(it + 1, (it + 1) & 1);
        else cp_commit();
        cp_wait1();
        __syncthreads();

        const float* Ks = sm + (it & 1) * FSTGW;
        const float* Vs = Ks + FBK * KSTW;
        float* Ps = sm + PSOFF;
        int kb = it * FBK;

        float sacc[4][4];
#pragma unroll
        for (int j = 0; j < 4; j++)
#pragma unroll
            for (int q = 0; q < 4; q++) sacc[j][q] = 0.f;

#pragma unroll
        for (int ks = 0; ks < 16; ks++) {
            int k0 = ks * 8;
#pragma unroll
            for (int j = 0; j < 4; j++) {
                uint32_t b0 = __float_as_uint(Ks[(j * 8 + gr) * KSTW + k0 + tg]);
                uint32_t b1 = __float_as_uint(Ks[(j * 8 + gr) * KSTW + k0 + 4 + tg]);
                mma_tf32(sacc[j], qf[ks], b0, b1);
            }
        }

        float tm0 = -CUDART_INF_F, tm1 = -CUDART_INF_F;
#pragma unroll
        for (int j = 0; j < 4; j++) {
            int kcol = kb + j * 8 + 2 * tg;
            if (kcol     > t0) sacc[j][0] = -CUDART_INF_F;
            if (kcol + 1 > t0) sacc[j][1] = -CUDART_INF_F;
            if (kcol     > t1) sacc[j][2] = -CUDART_INF_F;
            if (kcol + 1 > t1) sacc[j][3] = -CUDART_INF_F;
            tm0 = fmaxf(tm0, fmaxf(sacc[j][0], sacc[j][1]));
            tm1 = fmaxf(tm1, fmaxf(sacc[j][2], sacc[j][3]));
        }
        tm0 = fmaxf(tm0, __shfl_xor_sync(0xffffffffu, tm0, 1));
        tm0 = fmaxf(tm0, __shfl_xor_sync(0xffffffffu, tm0, 2));
        tm1 = fmaxf(tm1, __shfl_xor_sync(0xffffffffu, tm1, 1));
        tm1 = fmaxf(tm1, __shfl_xor_sync(0xffffffffu, tm1, 2));

        float mn0 = fmaxf(m0, tm0);
        float mn1 = fmaxf(m1, tm1);
        float c0 = __expf(m0 - mn0);
        float c1 = __expf(m1 - mn1);

        float ps0 = 0.f, ps1 = 0.f;
#pragma unroll
        for (int j = 0; j < 4; j++) {
            uint32_t p0 = f2tf32(__expf(sacc[j][0] - mn0));
            uint32_t p1 = f2tf32(__expf(sacc[j][1] - mn0));
            uint32_t p2 = f2tf32(__expf(sacc[j][2] - mn1));
            uint32_t p3 = f2tf32(__expf(sacc[j][3] - mn1));
            ps0 += __uint_as_float(p0) + __uint_as_float(p1);
            ps1 += __uint_as_float(p2) + __uint_as_float(p3);
            uint2 w0 = { p0, p1 };
            uint2 w1 = { p2, p3 };
            *(uint2*)(Ps + (wm + gr) * PST + j * 8 + 2 * tg)     = w0;
            *(uint2*)(Ps + (wm + 8 + gr) * PST + j * 8 + 2 * tg) = w1;
        }
        ps0 += __shfl_xor_sync(0xffffffffu, ps0, 1);
        ps0 += __shfl_xor_sync(0xffffffffu, ps0, 2);
        ps1 += __shfl_xor_sync(0xffffffffu, ps1, 1);
        ps1 += __shfl_xor_sync(0xffffffffu, ps1, 2);

        l0 = l0 * c0 + ps0;
        l1 = l1 * c1 + ps1;
        m0 = mn0; m1 = mn1;

#pragma unroll
        for (int f = 0; f < 16; f++) {
            oacc[f][0] *= c0; oacc[f][1] *= c0;
            oacc[f][2] *= c1; oacc[f][3] *= c1;
        }
        __syncwarp();

#pragma unroll
        for (int ks2 = 0; ks2 < 4; ks2++) {
            int k0 = ks2 * 8;
            uint32_t a[4];
            a[0] = __float_as_uint(Ps[(wm + gr) * PST + k0 + tg]);
            a[1] = __float_as_uint(Ps[(wm + 8 + gr) * PST + k0 + tg]);
            a[2] = __float_as_uint(Ps[(wm + gr) * PST + k0 + 4 + tg]);
            a[3] = __float_as_uint(Ps[(wm + 8 + gr) * PST + k0 + 4 + tg]);
#pragma unroll
            for (int f = 0; f < 16; f++) {
                uint32_t b0 = __float_as_uint(Vs[(k0 + tg) * VSTW + f * 8 + gr]);
                uint32_t b1 = __float_as_uint(Vs[(k0 + 4 + tg) * VSTW + f * 8 + gr]);
                mma_tf32(oacc[f], a, b0, b1);
            }
        }
        __syncthreads();
    }

    float inv0 = 1.0f / l0;
    float inv1 = 1.0f / l1;
    float* o0 = O + ((size_t)t0 * HQ + h) * HD;
    float* o1 = O + ((size_t)t1 * HQ + h) * HD;
#pragma unroll
    for (int f = 0; f < 16; f++) {
        int cc = f * 8 + 2 * tg;
        float2 v0 = { roundtf(oacc[f][0] * inv0), roundtf(oacc[f][1] * inv0) };
        float2 v1 = { roundtf(oacc[f][2] * inv1), roundtf(oacc[f][3] * inv1) };
        *(float2*)(o0 + cc) = v0;
        *(float2*)(o1 + cc) = v1;
    }
}

// ---------------------------------------------------------------------------
// Launch
// ---------------------------------------------------------------------------
extern "C" void kernel_launch(void* const* d_in, const int* in_sizes, int n_in,
                              void* d_out, int out_size)
{
    const float* x   = (const float*)d_in[0];
    const float* cs  = (const float*)d_in[1];
    const float* sn  = (const float*)d_in[2];
    const float* wq  = (const float*)d_in[3];
    const float* wk  = (const float*)d_in[4];
    const float* wv  = (const float*)d_in[5];
    const float* wo  = (const float*)d_in[6];
    float* out = (float*)d_out;

    float *pq, *pk, *pv, *patt, *pxr, *pwqr, *pwkr, *pwvr, *pwor;
    cudaGetSymbolAddress((void**)&pq,   g_q);
    cudaGetSymbolAddress((void**)&pk,   g_k);
    cudaGetSymbolAddress((void**)&pv,   g_v);
    cudaGetSymbolAddress((void**)&patt, g_att);
    cudaGetSymbolAddress((void**)&pxr,  g_xr);
    cudaGetSymbolAddress((void**)&pwqr, g_wqr);
    cudaGetSymbolAddress((void**)&pwkr, g_wkr);
    cudaGetSymbolAddress((void**)&pwvr, g_wvr);
    cudaGetSymbolAddress((void**)&pwor, g_wor);

    cudaFuncSetAttribute(gemm_async, cudaFuncAttributeMaxDynamicSharedMemorySize,
                         GEMM_SMEM);
    cudaFuncSetAttribute(flash_async, cudaFuncAttributeMaxDynamicSharedMemorySize,
                         FLASH_SMEM);

    // All tf32 pre-rounding in one launch
    round_all_kernel<<<2048, 256>>>(
        (const float4*)x,  (float4*)pxr,
        (const float4*)wq, (float4*)pwqr,
        (const float4*)wk, (float4*)pwkr,
        (const float4*)wv, (float4*)pwvr,
        (const float4*)wo, (float4*)pwor);

    // Q projection
    gemm_async<<<dim3(C_EMB / BN, T_SEQ / BM, 1), 256, GEMM_SMEM>>>(
        pxr, pwqr, pwqr, pq, pq, T_SEQ, C_EMB, C_EMB, 0);
    // K + V projections combined (z picks weight/output; V output rounded)
    gemm_async<<<dim3(KVD / BN, T_SEQ / BM, 2), 256, GEMM_SMEM>>>(
        pxr, pwkr, pwvr, pk, pv, T_SEQ, KVD, C_EMB, 1);

    // RoPE + RMSNorm on Q and K fused (K output tf32-rounded)
    rope_rms_fused<<<dim3(T_SEQ, (HQ + HKV) / 4), 256>>>(pq, pk, cs, sn);

    // Flash attention (output tf32-rounded)
    flash_async<<<dim3(T_SEQ / FBQ, HQ), 128, FLASH_SMEM>>>(pq, pk, pv, patt);

    // Output projection -> d_out
    gemm_async<<<dim3(C_EMB / BN, T_SEQ / BM, 1), 256, GEMM_SMEM>>>(
        patt, pwor, pwor, out, out, T_SEQ, C_EMB, C_EMB, 0);
}